// round 12
// baseline (speedup 1.0000x reference)
#include <cuda_runtime.h>
#include <cuda_bf16.h>

// x (8,3,512,512) f32, y (8,3,1024,1024) f32, w1,b1,w2,b2 (3,) f32.
// out_lr = sigmoid(w2 * boxsum3x3_dil2(relu(w1*x+b1)) + b2) * relu(w1*x+b1)
// output = y + nearest_upsample_x2(out_lr)
//
// R10 per-thread structure (4 px/thread, shuffle halos, v8 ld/st,
// y=.cs loads / write-back stores) with 128x4 blocks: each block owns
// 4 consecutive low-res rows -> 8 consecutive hi-res rows = contiguous
// 32KB y + 32KB out regions for better L2-sector / DRAM-page locality.

#define HH 512
#define WW 512
#define H2 1024
#define W2 1024
#define CC 3
#define RPB 4          // low-res rows per block (threadIdx.y)
#define FULL 0xFFFFFFFFu

__device__ __forceinline__ float actv(float v, float w1v, float b1v) {
    return fmaxf(fmaf(w1v, v, b1v), 0.0f);
}

// sigmoid(z) = 0.5 * tanh(0.5 z) + 0.5  (tanh.approx.f32 = single MUFU op)
__device__ __forceinline__ float fast_sigmoid(float z) {
    float t;
    asm("tanh.approx.f32 %0, %1;" : "=f"(t) : "f"(0.5f * z));
    return fmaf(0.5f, t, 0.5f);
}

// 256-bit global load (streaming) / store (default write-back), sm_100+
__device__ __forceinline__ void ldg256_cs(float* r, const float* p) {
    asm volatile("ld.global.cs.v8.f32 {%0,%1,%2,%3,%4,%5,%6,%7}, [%8];"
                 : "=f"(r[0]), "=f"(r[1]), "=f"(r[2]), "=f"(r[3]),
                   "=f"(r[4]), "=f"(r[5]), "=f"(r[6]), "=f"(r[7])
                 : "l"(p));
}
__device__ __forceinline__ void stg256(float* p, const float* r) {
    asm volatile("st.global.v8.f32 [%0], {%1,%2,%3,%4,%5,%6,%7,%8};"
                 :: "l"(p),
                    "f"(r[0]), "f"(r[1]), "f"(r[2]), "f"(r[3]),
                    "f"(r[4]), "f"(r[5]), "f"(r[6]), "f"(r[7])
                 : "memory");
}

__global__ __launch_bounds__(128 * RPB, 4)
void fused_shift_gate_up_kernel(const float* __restrict__ x,
                                const float* __restrict__ y,
                                const float* __restrict__ w1,
                                const float* __restrict__ b1,
                                const float* __restrict__ w2,
                                const float* __restrict__ b2,
                                float* __restrict__ out)
{
    const int tid   = threadIdx.x;                      // 0..127
    const int lane  = tid & 31;
    const int w0    = tid << 2;                         // low-res col base
    const int h     = blockIdx.y * RPB + threadIdx.y;   // low-res row
    const int plane = blockIdx.z;                       // b*C + c
    const int c     = plane % CC;

    const float w1v = __ldg(w1 + c);
    const float b1v = __ldg(b1 + c);
    const float w2v = __ldg(w2 + c);
    const float b2v = __ldg(b2 + c);

    const unsigned r0 = (unsigned)plane * (H2 * W2)
                      + ((unsigned)h << 1) * W2 + ((unsigned)w0 << 1);
    const unsigned r1 = r0 + W2;
    const float* xc_p = x + (unsigned)plane * (HH * WW)
                          + (unsigned)h * WW + (unsigned)w0;

    float s0 = 0.f, s1 = 0.f, s2 = 0.f, s3 = 0.f;   // dilated box sums
    float xc0 = 0.f, xc1 = 0.f, xc2 = 0.f, xc3 = 0.f;

    const bool edgeL = (lane == 0);
    const bool edgeR = (lane == 31);
    const bool okL   = (w0 >= 2);
    const bool okR   = (w0 + 5 < WW);

    #pragma unroll
    for (int dr = 0; dr < 3; ++dr) {
        const int r = h + (dr - 1) * 2;   // warp-uniform
        if ((unsigned)r < (unsigned)HH) {
            const float* row = xc_p + (dr - 1) * 2 * WW;

            float4 Cv = *reinterpret_cast<const float4*>(row);
            float a0 = actv(Cv.x, w1v, b1v);
            float a1 = actv(Cv.y, w1v, b1v);
            float a2 = actv(Cv.z, w1v, b1v);
            float a3 = actv(Cv.w, w1v, b1v);

            // Halos from neighbor lanes (already activated)
            float aL2 = __shfl_up_sync(FULL, a2, 1);    // a[w0-2]
            float aL1 = __shfl_up_sync(FULL, a3, 1);    // a[w0-1]
            float aR0 = __shfl_down_sync(FULL, a0, 1);  // a[w0+4]
            float aR1 = __shfl_down_sync(FULL, a1, 1);  // a[w0+5]

            if (edgeL) {
                aL2 = 0.f; aL1 = 0.f;
                if (okL) {
                    float2 L = *reinterpret_cast<const float2*>(row - 2);
                    aL2 = actv(L.x, w1v, b1v);
                    aL1 = actv(L.y, w1v, b1v);
                }
            }
            if (edgeR) {
                aR0 = 0.f; aR1 = 0.f;
                if (okR) {
                    float2 R = *reinterpret_cast<const float2*>(row + 4);
                    aR0 = actv(R.x, w1v, b1v);
                    aR1 = actv(R.y, w1v, b1v);
                }
            }

            const float t02 = a0 + a2;
            const float t13 = a1 + a3;
            s0 += aL2 + t02;
            s1 += aL1 + t13;
            s2 += t02 + aR0;
            s3 += t13 + aR1;
            if (dr == 1) { xc0 = a0; xc1 = a1; xc2 = a2; xc3 = a3; }
        }
    }

    const float o0 = xc0 * fast_sigmoid(fmaf(w2v, s0, b2v));
    const float o1 = xc1 * fast_sigmoid(fmaf(w2v, s1, b2v));
    const float o2 = xc2 * fast_sigmoid(fmaf(w2v, s2, b2v));
    const float o3 = xc3 * fast_sigmoid(fmaf(w2v, s3, b2v));

    float ya[8], yb[8];
    ldg256_cs(ya, y + r0);   // hi-res row 2h
    ldg256_cs(yb, y + r1);   // hi-res row 2h+1

    float ua[8], ub[8];
    ua[0] = ya[0] + o0; ua[1] = ya[1] + o0; ua[2] = ya[2] + o1; ua[3] = ya[3] + o1;
    ua[4] = ya[4] + o2; ua[5] = ya[5] + o2; ua[6] = ya[6] + o3; ua[7] = ya[7] + o3;
    ub[0] = yb[0] + o0; ub[1] = yb[1] + o0; ub[2] = yb[2] + o1; ub[3] = yb[3] + o1;
    ub[4] = yb[4] + o2; ub[5] = yb[5] + o2; ub[6] = yb[6] + o3; ub[7] = yb[7] + o3;

    stg256(out + r0, ua);
    stg256(out + r1, ub);
}

extern "C" void kernel_launch(void* const* d_in, const int* in_sizes, int n_in,
                              void* d_out, int out_size)
{
    const float* x  = (const float*)d_in[0];
    const float* y  = (const float*)d_in[1];
    const float* w1 = (const float*)d_in[2];
    const float* b1 = (const float*)d_in[3];
    const float* w2 = (const float*)d_in[4];
    const float* b2 = (const float*)d_in[5];
    float* out = (float*)d_out;

    dim3 grid(1, HH / RPB, 8 * CC);   // 128 row-groups x 24 planes = 3072 blocks
    dim3 block(128, RPB, 1);          // 512 threads: 128 cols x 4 rows
    fused_shift_gate_up_kernel<<<grid, block>>>(x, y, w1, b1, w2, b2, out);
}

// round 13
// speedup vs baseline: 1.0437x; 1.0437x over previous
#include <cuda_runtime.h>
#include <cuda_bf16.h>

// x (8,3,512,512) f32, y (8,3,1024,1024) f32, w1,b1,w2,b2 (3,) f32.
// out_lr = sigmoid(w2 * boxsum3x3_dil2(relu(w1*x+b1)) + b2) * relu(w1*x+b1)
// output = y + nearest_upsample_x2(out_lr)
//
// Champion structure: 4 px/thread, 128 thr/block, 12288 blocks, shuffle
// halos, 256-bit v8 ld/st on y/out. Cache policy: ALL DEFAULT (x default,
// y default, stores write-back) — completes the policy matrix after .cs
// stores (R9) and .cs loads (R10/R11) both failed to beat noise on replays.

#define HH 512
#define WW 512
#define H2 1024
#define W2 1024
#define CC 3
#define FULL 0xFFFFFFFFu

__device__ __forceinline__ float actv(float v, float w1v, float b1v) {
    return fmaxf(fmaf(w1v, v, b1v), 0.0f);
}

// sigmoid(z) = 0.5 * tanh(0.5 z) + 0.5  (tanh.approx.f32 = single MUFU op)
__device__ __forceinline__ float fast_sigmoid(float z) {
    float t;
    asm("tanh.approx.f32 %0, %1;" : "=f"(t) : "f"(0.5f * z));
    return fmaf(0.5f, t, 0.5f);
}

// 256-bit global load/store, default cache policy (sm_100+)
__device__ __forceinline__ void ldg256(float* r, const float* p) {
    asm volatile("ld.global.v8.f32 {%0,%1,%2,%3,%4,%5,%6,%7}, [%8];"
                 : "=f"(r[0]), "=f"(r[1]), "=f"(r[2]), "=f"(r[3]),
                   "=f"(r[4]), "=f"(r[5]), "=f"(r[6]), "=f"(r[7])
                 : "l"(p));
}
__device__ __forceinline__ void stg256(float* p, const float* r) {
    asm volatile("st.global.v8.f32 [%0], {%1,%2,%3,%4,%5,%6,%7,%8};"
                 :: "l"(p),
                    "f"(r[0]), "f"(r[1]), "f"(r[2]), "f"(r[3]),
                    "f"(r[4]), "f"(r[5]), "f"(r[6]), "f"(r[7])
                 : "memory");
}

__global__ __launch_bounds__(128, 16)
void fused_shift_gate_up_kernel(const float* __restrict__ x,
                                const float* __restrict__ y,
                                const float* __restrict__ w1,
                                const float* __restrict__ b1,
                                const float* __restrict__ w2,
                                const float* __restrict__ b2,
                                float* __restrict__ out)
{
    const int tid   = threadIdx.x;        // 0..127
    const int lane  = tid & 31;
    const int w0    = tid << 2;           // low-res column base (mult of 4)
    const int h     = blockIdx.y;         // low-res row
    const int plane = blockIdx.z;         // b*C + c
    const int c     = plane % CC;

    const float w1v = __ldg(w1 + c);
    const float b1v = __ldg(b1 + c);
    const float w2v = __ldg(w2 + c);
    const float b2v = __ldg(b2 + c);

    const unsigned r0 = (unsigned)plane * (H2 * W2)
                      + ((unsigned)h << 1) * W2 + ((unsigned)w0 << 1);
    const unsigned r1 = r0 + W2;
    const float* xc_p = x + (unsigned)plane * (HH * WW)
                          + (unsigned)h * WW + (unsigned)w0;

    float s0 = 0.f, s1 = 0.f, s2 = 0.f, s3 = 0.f;   // dilated box sums
    float xc0 = 0.f, xc1 = 0.f, xc2 = 0.f, xc3 = 0.f;

    const bool edgeL = (lane == 0);
    const bool edgeR = (lane == 31);
    const bool okL   = (w0 >= 2);
    const bool okR   = (w0 + 5 < WW);

    #pragma unroll
    for (int dr = 0; dr < 3; ++dr) {
        const int r = h + (dr - 1) * 2;   // warp-uniform
        if ((unsigned)r < (unsigned)HH) {
            const float* row = xc_p + (dr - 1) * 2 * WW;

            float4 Cv = *reinterpret_cast<const float4*>(row);
            float a0 = actv(Cv.x, w1v, b1v);
            float a1 = actv(Cv.y, w1v, b1v);
            float a2 = actv(Cv.z, w1v, b1v);
            float a3 = actv(Cv.w, w1v, b1v);

            // Halos from neighbor lanes (already activated)
            float aL2 = __shfl_up_sync(FULL, a2, 1);    // a[w0-2]
            float aL1 = __shfl_up_sync(FULL, a3, 1);    // a[w0-1]
            float aR0 = __shfl_down_sync(FULL, a0, 1);  // a[w0+4]
            float aR1 = __shfl_down_sync(FULL, a1, 1);  // a[w0+5]

            if (edgeL) {
                aL2 = 0.f; aL1 = 0.f;
                if (okL) {
                    float2 L = *reinterpret_cast<const float2*>(row - 2);
                    aL2 = actv(L.x, w1v, b1v);
                    aL1 = actv(L.y, w1v, b1v);
                }
            }
            if (edgeR) {
                aR0 = 0.f; aR1 = 0.f;
                if (okR) {
                    float2 R = *reinterpret_cast<const float2*>(row + 4);
                    aR0 = actv(R.x, w1v, b1v);
                    aR1 = actv(R.y, w1v, b1v);
                }
            }

            const float t02 = a0 + a2;
            const float t13 = a1 + a3;
            s0 += aL2 + t02;
            s1 += aL1 + t13;
            s2 += t02 + aR0;
            s3 += t13 + aR1;
            if (dr == 1) { xc0 = a0; xc1 = a1; xc2 = a2; xc3 = a3; }
        }
    }

    const float o0 = xc0 * fast_sigmoid(fmaf(w2v, s0, b2v));
    const float o1 = xc1 * fast_sigmoid(fmaf(w2v, s1, b2v));
    const float o2 = xc2 * fast_sigmoid(fmaf(w2v, s2, b2v));
    const float o3 = xc3 * fast_sigmoid(fmaf(w2v, s3, b2v));

    float ya[8], yb[8];
    ldg256(ya, y + r0);   // hi-res row 2h
    ldg256(yb, y + r1);   // hi-res row 2h+1

    float ua[8], ub[8];
    ua[0] = ya[0] + o0; ua[1] = ya[1] + o0; ua[2] = ya[2] + o1; ua[3] = ya[3] + o1;
    ua[4] = ya[4] + o2; ua[5] = ya[5] + o2; ua[6] = ya[6] + o3; ua[7] = ya[7] + o3;
    ub[0] = yb[0] + o0; ub[1] = yb[1] + o0; ub[2] = yb[2] + o1; ub[3] = yb[3] + o1;
    ub[4] = yb[4] + o2; ub[5] = yb[5] + o2; ub[6] = yb[6] + o3; ub[7] = yb[7] + o3;

    stg256(out + r0, ua);
    stg256(out + r1, ub);
}

extern "C" void kernel_launch(void* const* d_in, const int* in_sizes, int n_in,
                              void* d_out, int out_size)
{
    const float* x  = (const float*)d_in[0];
    const float* y  = (const float*)d_in[1];
    const float* w1 = (const float*)d_in[2];
    const float* b1 = (const float*)d_in[3];
    const float* w2 = (const float*)d_in[4];
    const float* b2 = (const float*)d_in[5];
    float* out = (float*)d_out;

    dim3 grid(1, HH, 8 * CC);   // one block per low-res row per plane
    dim3 block(128, 1, 1);      // 128 threads x 4 low-res cols = 512
    fused_shift_gate_up_kernel<<<grid, block>>>(x, y, w1, b1, w2, b2, out);
}